// round 13
// baseline (speedup 1.0000x reference)
#include <cuda_runtime.h>
#include <cstddef>

// LocalVariation: out[b,k,y,x] = x[b,y,x] - x[b, clamp(y+i-2), clamp(x+j-2)]
// k enumerates 24 off-center (i,j) in a 5x5 window. x: [16,1,512,512] f32.
//
// R8: continue the granularity trend (each halving of per-CTA duration has
// halved the final-wave tail cost): 1 row / 128 threads per CTA -> 8192 CTAs,
// per-CTA ~3.3us. SMEM-free register gather (R6), 24 streaming STG.128 per
// thread unchanged.

#define KSZ 5
#define P   2
#define NBR 24
#define H   512
#define W   512
#define BATCH 16

__global__ __launch_bounds__(128, 12)
void LocalVariation_kernel(const float* __restrict__ x, float* __restrict__ out)
{
    const int tid = threadIdx.x;                  // 0..127
    const int x0  = tid * 4;                      // 4 pixels per thread
    const int y   = blockIdx.x;                   // 0..511
    const int b   = blockIdx.y;                   // 0..15

    const float* __restrict__ xb = x + (size_t)b * (H * W);

    // Center 4 pixels: aligned LDG.128 at (y, x0).
    const float4 cv = __ldg(reinterpret_cast<const float4*>(xb + y * W + x0));
    const float c0 = cv.x, c1 = cv.y, c2 = cv.z, c3 = cv.w;

    float* __restrict__ ob =
        out + (((size_t)b * NBR) * H + y) * W + x0;

    const bool has_lo = (x0 > 0);        // left  window part in-row?
    const bool has_hi = (x0 < W - 4);    // right window part in-row?

    int k = 0;
    #pragma unroll
    for (int i = 0; i < KSZ; i++) {
        int gy = y + i - P;
        gy = gy < 0 ? 0 : (gy > H - 1 ? H - 1 : gy);
        const float* __restrict__ rp = xb + gy * W;

        // Window w[m] = row value at x = clamp(x0 - 2 + m), m = 0..7.
        const float4 v1 = __ldg(reinterpret_cast<const float4*>(rp + x0));
        float w0, w1, w6, w7;
        if (has_lo) {
            const float4 v0 = __ldg(reinterpret_cast<const float4*>(rp + x0 - 4));
            w0 = v0.z; w1 = v0.w;                 // x0-2, x0-1
        } else {
            w0 = v1.x; w1 = v1.x;                 // replicate pad: clamp to x=0
        }
        if (has_hi) {
            const float4 v2 = __ldg(reinterpret_cast<const float4*>(rp + x0 + 4));
            w6 = v2.x; w7 = v2.y;                 // x0+4, x0+5
        } else {
            w6 = v1.w; w7 = v1.w;                 // clamp to x=511
        }
        const float w2 = v1.x, w3 = v1.y, w4 = v1.z, w5 = v1.w;

        #pragma unroll
        for (int j = 0; j < KSZ; j++) {
            if (i == P && j == P) continue;
            // neighbor for output pixel dx is w[dx + j]
            const float n0 = (j == 0) ? w0 : (j == 1) ? w1 : (j == 2) ? w2 : (j == 3) ? w3 : w4;
            const float n1 = (j == 0) ? w1 : (j == 1) ? w2 : (j == 2) ? w3 : (j == 3) ? w4 : w5;
            const float n2 = (j == 0) ? w2 : (j == 1) ? w3 : (j == 2) ? w4 : (j == 3) ? w5 : w6;
            const float n3 = (j == 0) ? w3 : (j == 1) ? w4 : (j == 2) ? w5 : (j == 3) ? w6 : w7;
            float4 v;
            v.x = c0 - n0;
            v.y = c1 - n1;
            v.z = c2 - n2;
            v.w = c3 - n3;
            __stcs(reinterpret_cast<float4*>(ob + (size_t)k * (H * W)), v);
            k++;
        }
    }
}

extern "C" void kernel_launch(void* const* d_in, const int* in_sizes, int n_in,
                              void* d_out, int out_size)
{
    (void)in_sizes; (void)n_in; (void)out_size;
    const float* x = (const float*)d_in[0];
    float* out = (float*)d_out;
    dim3 grid(H, BATCH);
    LocalVariation_kernel<<<grid, 128>>>(x, out);
}